// round 4
// baseline (speedup 1.0000x reference)
#include <cuda_runtime.h>

#define N_NODES 50000
#define N_EDGES 800000
#define NFEAT 128
#define NHID 128
#define NOUT 64

// ---------------- scratch (static __device__, no allocations) ----------------
__device__ __align__(16) float g_support[N_NODES * 128];
__device__ __align__(16) float g_h[N_NODES * 128];
__device__ int   g_rowptr[N_NODES + 1];
__device__ int   g_cursor[N_NODES];
__device__ int   g_csr_src[N_EDGES];
__device__ float g_csr_w[N_EDGES];

// ---------------- CSR build ----------------
__global__ void zero_cursor_kernel() {
    int i = blockIdx.x * blockDim.x + threadIdx.x;
    if (i < N_NODES) g_cursor[i] = 0;
}

__global__ void hist_kernel(const int* __restrict__ dst) {
    int e = blockIdx.x * blockDim.x + threadIdx.x;
    if (e < N_EDGES) atomicAdd(&g_cursor[dst[e]], 1);
}

// single-block exclusive scan over 50000 counts (1024 threads, chunked)
__global__ void scan_kernel() {
    __shared__ int sdata[1024];
    const int tid = threadIdx.x;
    int carry = 0;
    for (int base = 0; base < N_NODES; base += 1024) {
        int i = base + tid;
        int v = (i < N_NODES) ? g_cursor[i] : 0;
        sdata[tid] = v;
        __syncthreads();
        int val = v;
        for (int off = 1; off < 1024; off <<= 1) {
            int t = (tid >= off) ? sdata[tid - off] : 0;
            __syncthreads();
            val += t;
            sdata[tid] = val;
            __syncthreads();
        }
        if (i < N_NODES) g_rowptr[i] = carry + val - v;  // exclusive
        int tot = sdata[1023];
        __syncthreads();
        carry += tot;
    }
    if (tid == 0) g_rowptr[N_NODES] = carry;
}

__global__ void scatter_kernel(const int* __restrict__ src,
                               const int* __restrict__ dst,
                               const float* __restrict__ w) {
    int e = blockIdx.x * blockDim.x + threadIdx.x;
    if (e < N_EDGES) {
        int d = dst[e];
        int pos = g_rowptr[d] + atomicAdd(&g_cursor[d], 1);
        g_csr_src[pos] = src[e];
        g_csr_w[pos]   = w[e];
    }
}

// ---------------- dense GEMM: C[M,BN] = A[M,128] @ B[128,BN] ----------------
// BM=128 rows per block, BK=32 k-slab, 256 threads, 8x(BN/16) register tile.
template <int BN>
__global__ void __launch_bounds__(256, 1)
gemm_kernel(const float* __restrict__ A, const float* __restrict__ B,
            float* __restrict__ C, int M) {
    constexpr int K = 128, BM = 128, BK = 32;
    constexpr int TM = 8, TN = BN / 16;

    __shared__ float As[BK][BM];   // transposed: As[k][m]
    __shared__ float Bs[BK][BN];   // natural:    Bs[k][n]

    const int tid = threadIdx.x;
    const int m0  = blockIdx.x * BM;
    const int tx  = tid % 16;
    const int ty  = tid / 16;
    const int mm  = ty * TM;
    const int nn  = tx * TN;

    float acc[TM][TN];
#pragma unroll
    for (int i = 0; i < TM; i++)
#pragma unroll
        for (int j = 0; j < TN; j++) acc[i][j] = 0.0f;

    const float4* A4 = reinterpret_cast<const float4*>(A);
    const float4* B4 = reinterpret_cast<const float4*>(B);

    for (int k0 = 0; k0 < K; k0 += BK) {
        // Load A slab (BM x BK) transposed into As[k][m]. m varies fastest
        // across lanes -> conflict-free STS; global reads are strided but
        // L2-resident, negligible vs compute.
#pragma unroll
        for (int it = 0; it < (BM * BK / 4) / 256; it++) {
            int f  = tid + it * 256;
            int m  = f & (BM - 1);
            int kq = f >> 7;              // 0..BK/4-1
            int gm = m0 + m;
            float4 v = make_float4(0.f, 0.f, 0.f, 0.f);
            if (gm < M) v = A4[gm * (K / 4) + (k0 / 4) + kq];
            int k = kq * 4;
            As[k + 0][m] = v.x;
            As[k + 1][m] = v.y;
            As[k + 2][m] = v.z;
            As[k + 3][m] = v.w;
        }
        // Load B slab (BK x BN), contiguous
#pragma unroll
        for (int f = tid; f < BK * BN / 4; f += 256) {
            reinterpret_cast<float4*>(&Bs[0][0])[f] = B4[k0 * (BN / 4) + f];
        }
        __syncthreads();

#pragma unroll 4
        for (int k = 0; k < BK; k++) {
            float a[TM];
            float4 a0 = *reinterpret_cast<const float4*>(&As[k][mm]);
            float4 a1 = *reinterpret_cast<const float4*>(&As[k][mm + 4]);
            a[0] = a0.x; a[1] = a0.y; a[2] = a0.z; a[3] = a0.w;
            a[4] = a1.x; a[5] = a1.y; a[6] = a1.z; a[7] = a1.w;
            float b[TN];
#pragma unroll
            for (int j4 = 0; j4 < TN / 4; j4++) {
                float4 bv = *reinterpret_cast<const float4*>(&Bs[k][nn + j4 * 4]);
                b[j4 * 4 + 0] = bv.x; b[j4 * 4 + 1] = bv.y;
                b[j4 * 4 + 2] = bv.z; b[j4 * 4 + 3] = bv.w;
            }
#pragma unroll
            for (int i = 0; i < TM; i++)
#pragma unroll
                for (int j = 0; j < TN; j++) acc[i][j] += a[i] * b[j];
        }
        __syncthreads();
    }

    // epilogue
#pragma unroll
    for (int i = 0; i < TM; i++) {
        int row = m0 + mm + i;
        if (row < M) {
#pragma unroll
            for (int j4 = 0; j4 < TN / 4; j4++) {
                float4 v;
                v.x = acc[i][j4 * 4 + 0];
                v.y = acc[i][j4 * 4 + 1];
                v.z = acc[i][j4 * 4 + 2];
                v.w = acc[i][j4 * 4 + 3];
                reinterpret_cast<float4*>(&C[row * BN])[nn / 4 + j4] = v;
            }
        }
    }
}

// ---------------- SpMM (CSR-by-dst) + bias (+ReLU) ----------------
// one warp per destination node; lane owns D/32 consecutive channels.
template <int D, bool RELU>
__global__ void spmm_kernel(const float* __restrict__ sup,
                            const float* __restrict__ bias,
                            float* __restrict__ out) {
    int gw = (blockIdx.x * blockDim.x + threadIdx.x) >> 5;
    if (gw >= N_NODES) return;
    int lane = threadIdx.x & 31;
    int s = g_rowptr[gw];
    int e = g_rowptr[gw + 1];

    if constexpr (D == 128) {
        const float4* supv = reinterpret_cast<const float4*>(sup);
        float4 acc = make_float4(0.f, 0.f, 0.f, 0.f);
        int i = s;
        for (; i + 1 < e; i += 2) {
            int   s0 = g_csr_src[i];     float w0 = g_csr_w[i];
            int   s1 = g_csr_src[i + 1]; float w1 = g_csr_w[i + 1];
            float4 v0 = supv[s0 * 32 + lane];
            float4 v1 = supv[s1 * 32 + lane];
            acc.x += w0 * v0.x + w1 * v1.x;
            acc.y += w0 * v0.y + w1 * v1.y;
            acc.z += w0 * v0.z + w1 * v1.z;
            acc.w += w0 * v0.w + w1 * v1.w;
        }
        if (i < e) {
            int s0 = g_csr_src[i]; float w0 = g_csr_w[i];
            float4 v0 = supv[s0 * 32 + lane];
            acc.x += w0 * v0.x; acc.y += w0 * v0.y;
            acc.z += w0 * v0.z; acc.w += w0 * v0.w;
        }
        float4 b = reinterpret_cast<const float4*>(bias)[lane];
        acc.x += b.x; acc.y += b.y; acc.z += b.z; acc.w += b.w;
        if (RELU) {
            acc.x = fmaxf(acc.x, 0.f); acc.y = fmaxf(acc.y, 0.f);
            acc.z = fmaxf(acc.z, 0.f); acc.w = fmaxf(acc.w, 0.f);
        }
        reinterpret_cast<float4*>(out)[gw * 32 + lane] = acc;
    } else {  // D == 64
        const float2* supv = reinterpret_cast<const float2*>(sup);
        float2 acc = make_float2(0.f, 0.f);
        int i = s;
        for (; i + 1 < e; i += 2) {
            int   s0 = g_csr_src[i];     float w0 = g_csr_w[i];
            int   s1 = g_csr_src[i + 1]; float w1 = g_csr_w[i + 1];
            float2 v0 = supv[s0 * 32 + lane];
            float2 v1 = supv[s1 * 32 + lane];
            acc.x += w0 * v0.x + w1 * v1.x;
            acc.y += w0 * v0.y + w1 * v1.y;
        }
        if (i < e) {
            int s0 = g_csr_src[i]; float w0 = g_csr_w[i];
            float2 v0 = supv[s0 * 32 + lane];
            acc.x += w0 * v0.x; acc.y += w0 * v0.y;
        }
        float2 b = reinterpret_cast<const float2*>(bias)[lane];
        acc.x += b.x; acc.y += b.y;
        if (RELU) { acc.x = fmaxf(acc.x, 0.f); acc.y = fmaxf(acc.y, 0.f); }
        reinterpret_cast<float2*>(out)[gw * 32 + lane] = acc;
    }
}

// ---------------- launch ----------------
extern "C" void kernel_launch(void* const* d_in, const int* in_sizes, int n_in,
                              void* d_out, int out_size) {
    const float* x        = (const float*)d_in[0];
    const int*   edge_src = (const int*)  d_in[1];
    const int*   edge_dst = (const int*)  d_in[2];
    const float* edge_w   = (const float*)d_in[3];
    const float* W0 = (const float*)d_in[4];  const float* b0 = (const float*)d_in[5];
    const float* W1 = (const float*)d_in[6];  const float* b1 = (const float*)d_in[7];
    const float* W2 = (const float*)d_in[8];  const float* b2 = (const float*)d_in[9];
    const float* W3 = (const float*)d_in[10]; const float* b3 = (const float*)d_in[11];
    float* out = (float*)d_out;

    float* support; cudaGetSymbolAddress((void**)&support, g_support);
    float* h;       cudaGetSymbolAddress((void**)&h, g_h);

    const int NB_NODE = (N_NODES + 255) / 256;
    const int NB_EDGE = (N_EDGES + 255) / 256;
    const int NB_GEMM = (N_NODES + 127) / 128;
    const int NB_SPMM = (N_NODES + 7) / 8;     // 8 warps/block

    // CSR build (per launch; amortized over 4 layers)
    zero_cursor_kernel<<<NB_NODE, 256>>>();
    hist_kernel<<<NB_EDGE, 256>>>(edge_dst);
    scan_kernel<<<1, 1024>>>();
    zero_cursor_kernel<<<NB_NODE, 256>>>();
    scatter_kernel<<<NB_EDGE, 256>>>(edge_src, edge_dst, edge_w);

    // layer 0: x -> h
    gemm_kernel<128><<<NB_GEMM, 256>>>(x, W0, support, N_NODES);
    spmm_kernel<128, true><<<NB_SPMM, 256>>>(support, b0, h);
    // layer 1
    gemm_kernel<128><<<NB_GEMM, 256>>>(h, W1, support, N_NODES);
    spmm_kernel<128, true><<<NB_SPMM, 256>>>(support, b1, h);
    // layer 2
    gemm_kernel<128><<<NB_GEMM, 256>>>(h, W2, support, N_NODES);
    spmm_kernel<128, true><<<NB_SPMM, 256>>>(support, b2, h);
    // layer 3 (d=64, no relu) -> d_out
    gemm_kernel<64><<<NB_GEMM, 256>>>(h, W3, support, N_NODES);
    spmm_kernel<64, false><<<NB_SPMM, 256>>>(support, b3, out);
}

// round 6
// speedup vs baseline: 1.0269x; 1.0269x over previous
#include <cuda_runtime.h>

#define N_NODES 50000
#define N_EDGES 800000
#define NFEAT 128
#define NHID 128
#define NOUT 64

// ---------------- scratch (static __device__, no allocations) ----------------
__device__ __align__(16) float g_support[N_NODES * 128];
__device__ __align__(16) float g_h[N_NODES * 128];
__device__ int   g_rowptr[N_NODES + 1];
__device__ int   g_cursor[N_NODES];
__device__ int   g_blocksum[128];
__device__ int   g_csr_src[N_EDGES];
__device__ float g_csr_w[N_EDGES];

// ---------------- f32x2 helpers (FFMA2 path, sm_103a) ----------------
__device__ __forceinline__ void ffma2(unsigned long long& d,
                                      unsigned long long a,
                                      unsigned long long b) {
    asm("fma.rn.f32x2 %0, %1, %2, %0;" : "+l"(d) : "l"(a), "l"(b));
}
__device__ __forceinline__ unsigned long long dup2(float x) {
    unsigned long long r;
    asm("mov.b64 %0, {%1, %1};" : "=l"(r) : "f"(x));
    return r;
}

// ---------------- CSR build ----------------
__global__ void zero_cursor_kernel() {
    int i = blockIdx.x * blockDim.x + threadIdx.x;
    if (i < N_NODES) g_cursor[i] = 0;
}

__global__ void hist_kernel(const int* __restrict__ dst) {
    int e = blockIdx.x * blockDim.x + threadIdx.x;
    if (e < N_EDGES) atomicAdd(&g_cursor[dst[e]], 1);
}

// phase 1: per-block inclusive scan of 512 counts -> exclusive partials + block total
__global__ void scan_blocks_kernel() {
    __shared__ int sdata[512];
    const int tid = threadIdx.x;
    int i = blockIdx.x * 512 + tid;
    int v = (i < N_NODES) ? g_cursor[i] : 0;
    sdata[tid] = v;
    __syncthreads();
#pragma unroll
    for (int off = 1; off < 512; off <<= 1) {
        int t = (tid >= off) ? sdata[tid - off] : 0;
        __syncthreads();
        sdata[tid] += t;
        __syncthreads();
    }
    if (i < N_NODES) g_rowptr[i] = sdata[tid] - v;  // block-local exclusive
    if (tid == 511) g_blocksum[blockIdx.x] = sdata[511];
}

// phase 2: single block scans the (<=128) block totals -> exclusive offsets
__global__ void scan_tops_kernel(int nblk) {
    __shared__ int sdata[128];
    const int tid = threadIdx.x;
    int v = (tid < nblk) ? g_blocksum[tid] : 0;
    sdata[tid] = v;
    __syncthreads();
#pragma unroll
    for (int off = 1; off < 128; off <<= 1) {
        int t = (tid >= off) ? sdata[tid - off] : 0;
        __syncthreads();
        sdata[tid] += t;
        __syncthreads();
    }
    if (tid < nblk) g_blocksum[tid] = sdata[tid] - v;  // exclusive
}

// phase 3: add block offsets; fused cursor re-zero; rowptr[N] = N_EDGES
__global__ void add_offsets_kernel() {
    int i = blockIdx.x * 512 + threadIdx.x;
    if (i < N_NODES) {
        g_rowptr[i] += g_blocksum[blockIdx.x];
        g_cursor[i] = 0;
    }
    if (i == 0) g_rowptr[N_NODES] = N_EDGES;
}

__global__ void scatter_kernel(const int* __restrict__ src,
                               const int* __restrict__ dst,
                               const float* __restrict__ w) {
    int e = blockIdx.x * blockDim.x + threadIdx.x;
    if (e < N_EDGES) {
        int d = dst[e];
        int pos = g_rowptr[d] + atomicAdd(&g_cursor[d], 1);
        g_csr_src[pos] = src[e];
        g_csr_w[pos]   = w[e];
    }
}

// ---------------- dense GEMM: C[M,BN] = A[M,128] @ B[128,BN] ----------------
// BM=128, BK=32, 256 threads, 8x(BN/16) register tile, FFMA2 (f32x2) math.
// A slab is stored in smem pre-duplicated as u64 {a,a} pairs so the inner
// loop is LDS.128 (warp-broadcast on the A side) + FFMA2 only.
template <int BN>
__global__ void __launch_bounds__(256, 1)
gemm_kernel(const float* __restrict__ A, const float* __restrict__ B,
            float* __restrict__ C, int M) {
    constexpr int K = 128, BM = 128, BK = 32;
    constexpr int TM = 8, TN = BN / 16, TN2 = TN / 2;

    __shared__ unsigned long long As2[BK][BM];  // 32 KB: As2[k][m] = {A,A}
    __shared__ float Bs[BK][BN];                // 16 KB (BN=128)

    const int tid = threadIdx.x;
    const int m0  = blockIdx.x * BM;
    const int tx  = tid % 16;
    const int ty  = tid / 16;
    const int mm  = ty * TM;
    const int nn  = tx * TN;

    unsigned long long acc2[TM][TN2];
#pragma unroll
    for (int i = 0; i < TM; i++)
#pragma unroll
        for (int j = 0; j < TN2; j++) acc2[i][j] = 0ull;

    const float4* A4 = reinterpret_cast<const float4*>(A);
    const float4* B4 = reinterpret_cast<const float4*>(B);

    for (int k0 = 0; k0 < K; k0 += BK) {
        // A slab (BM x BK) -> As2[k][m] duplicated pairs
#pragma unroll
        for (int it = 0; it < (BM * BK / 4) / 256; it++) {
            int f  = tid + it * 256;
            int m  = f & (BM - 1);
            int kq = f >> 7;              // 0..BK/4-1
            int gm = m0 + m;
            float4 v = make_float4(0.f, 0.f, 0.f, 0.f);
            if (gm < M) v = A4[gm * (K / 4) + (k0 / 4) + kq];
            int k = kq * 4;
            As2[k + 0][m] = dup2(v.x);
            As2[k + 1][m] = dup2(v.y);
            As2[k + 2][m] = dup2(v.z);
            As2[k + 3][m] = dup2(v.w);
        }
        // B slab (BK x BN), contiguous
#pragma unroll
        for (int f = tid; f < BK * BN / 4; f += 256) {
            reinterpret_cast<float4*>(&Bs[0][0])[f] = B4[k0 * (BN / 4) + f];
        }
        __syncthreads();

#pragma unroll 4
        for (int k = 0; k < BK; k++) {
            unsigned long long a2[TM];
#pragma unroll
            for (int i2 = 0; i2 < TM / 2; i2++) {
                ulonglong2 av = *reinterpret_cast<const ulonglong2*>(&As2[k][mm + i2 * 2]);
                a2[i2 * 2 + 0] = av.x;
                a2[i2 * 2 + 1] = av.y;
            }
            unsigned long long b2[TN2];
#pragma unroll
            for (int j4 = 0; j4 < TN2 / 2; j4++) {
                ulonglong2 bv = *reinterpret_cast<const ulonglong2*>(&Bs[k][nn + j4 * 4]);
                b2[j4 * 2 + 0] = bv.x;
                b2[j4 * 2 + 1] = bv.y;
            }
#pragma unroll
            for (int i = 0; i < TM; i++)
#pragma unroll
                for (int j = 0; j < TN2; j++) ffma2(acc2[i][j], a2[i], b2[j]);
        }
        __syncthreads();
    }

    // epilogue: each u64 pair is two adjacent output floats
#pragma unroll
    for (int i = 0; i < TM; i++) {
        int row = m0 + mm + i;
        if (row < M) {
#pragma unroll
            for (int j4 = 0; j4 < TN2 / 2; j4++) {
                ulonglong2 o;
                o.x = acc2[i][j4 * 2 + 0];
                o.y = acc2[i][j4 * 2 + 1];
                *reinterpret_cast<ulonglong2*>(&C[row * BN + nn + j4 * 4]) = o;
            }
        }
    }
}

// ---------------- SpMM (CSR-by-dst) + bias (+ReLU) ----------------
// one warp per destination node; lane owns D/32 consecutive channels.
template <int D, bool RELU>
__global__ void spmm_kernel(const float* __restrict__ sup,
                            const float* __restrict__ bias,
                            float* __restrict__ out) {
    int gw = (blockIdx.x * blockDim.x + threadIdx.x) >> 5;
    if (gw >= N_NODES) return;
    int lane = threadIdx.x & 31;
    int s = g_rowptr[gw];
    int e = g_rowptr[gw + 1];

    if constexpr (D == 128) {
        const float4* supv = reinterpret_cast<const float4*>(sup);
        float4 acc = make_float4(0.f, 0.f, 0.f, 0.f);
        int i = s;
        for (; i + 3 < e; i += 4) {
            int   s0 = g_csr_src[i];     float w0 = g_csr_w[i];
            int   s1 = g_csr_src[i + 1]; float w1 = g_csr_w[i + 1];
            int   s2 = g_csr_src[i + 2]; float w2 = g_csr_w[i + 2];
            int   s3 = g_csr_src[i + 3]; float w3 = g_csr_w[i + 3];
            float4 v0 = supv[s0 * 32 + lane];
            float4 v1 = supv[s1 * 32 + lane];
            float4 v2 = supv[s2 * 32 + lane];
            float4 v3 = supv[s3 * 32 + lane];
            acc.x += w0 * v0.x + w1 * v1.x + w2 * v2.x + w3 * v3.x;
            acc.y += w0 * v0.y + w1 * v1.y + w2 * v2.y + w3 * v3.y;
            acc.z += w0 * v0.z + w1 * v1.z + w2 * v2.z + w3 * v3.z;
            acc.w += w0 * v0.w + w1 * v1.w + w2 * v2.w + w3 * v3.w;
        }
        for (; i < e; i++) {
            int s0 = g_csr_src[i]; float w0 = g_csr_w[i];
            float4 v0 = supv[s0 * 32 + lane];
            acc.x += w0 * v0.x; acc.y += w0 * v0.y;
            acc.z += w0 * v0.z; acc.w += w0 * v0.w;
        }
        float4 b = reinterpret_cast<const float4*>(bias)[lane];
        acc.x += b.x; acc.y += b.y; acc.z += b.z; acc.w += b.w;
        if (RELU) {
            acc.x = fmaxf(acc.x, 0.f); acc.y = fmaxf(acc.y, 0.f);
            acc.z = fmaxf(acc.z, 0.f); acc.w = fmaxf(acc.w, 0.f);
        }
        reinterpret_cast<float4*>(out)[gw * 32 + lane] = acc;
    } else {  // D == 64
        const float2* supv = reinterpret_cast<const float2*>(sup);
        float2 acc = make_float2(0.f, 0.f);
        int i = s;
        for (; i + 3 < e; i += 4) {
            int   s0 = g_csr_src[i];     float w0 = g_csr_w[i];
            int   s1 = g_csr_src[i + 1]; float w1 = g_csr_w[i + 1];
            int   s2 = g_csr_src[i + 2]; float w2 = g_csr_w[i + 2];
            int   s3 = g_csr_src[i + 3]; float w3 = g_csr_w[i + 3];
            float2 v0 = supv[s0 * 32 + lane];
            float2 v1 = supv[s1 * 32 + lane];
            float2 v2 = supv[s2 * 32 + lane];
            float2 v3 = supv[s3 * 32 + lane];
            acc.x += w0 * v0.x + w1 * v1.x + w2 * v2.x + w3 * v3.x;
            acc.y += w0 * v0.y + w1 * v1.y + w2 * v2.y + w3 * v3.y;
        }
        for (; i < e; i++) {
            int s0 = g_csr_src[i]; float w0 = g_csr_w[i];
            float2 v0 = supv[s0 * 32 + lane];
            acc.x += w0 * v0.x; acc.y += w0 * v0.y;
        }
        float2 b = reinterpret_cast<const float2*>(bias)[lane];
        acc.x += b.x; acc.y += b.y;
        if (RELU) { acc.x = fmaxf(acc.x, 0.f); acc.y = fmaxf(acc.y, 0.f); }
        reinterpret_cast<float2*>(out)[gw * 32 + lane] = acc;
    }
}

// ---------------- launch ----------------
extern "C" void kernel_launch(void* const* d_in, const int* in_sizes, int n_in,
                              void* d_out, int out_size) {
    const float* x        = (const float*)d_in[0];
    const int*   edge_src = (const int*)  d_in[1];
    const int*   edge_dst = (const int*)  d_in[2];
    const float* edge_w   = (const float*)d_in[3];
    const float* W0 = (const float*)d_in[4];  const float* b0 = (const float*)d_in[5];
    const float* W1 = (const float*)d_in[6];  const float* b1 = (const float*)d_in[7];
    const float* W2 = (const float*)d_in[8];  const float* b2 = (const float*)d_in[9];
    const float* W3 = (const float*)d_in[10]; const float* b3 = (const float*)d_in[11];
    float* out = (float*)d_out;

    float* support; cudaGetSymbolAddress((void**)&support, g_support);
    float* h;       cudaGetSymbolAddress((void**)&h, g_h);

    const int NB_NODE = (N_NODES + 255) / 256;
    const int NB_EDGE = (N_EDGES + 255) / 256;
    const int NB_GEMM = (N_NODES + 127) / 128;
    const int NB_SPMM = (N_NODES + 7) / 8;      // 8 warps/block
    const int NB_SCAN = (N_NODES + 511) / 512;  // 98

    // CSR build (per launch; amortized over 4 layers)
    zero_cursor_kernel<<<NB_NODE, 256>>>();
    hist_kernel<<<NB_EDGE, 256>>>(edge_dst);
    scan_blocks_kernel<<<NB_SCAN, 512>>>();
    scan_tops_kernel<<<1, 128>>>(NB_SCAN);
    add_offsets_kernel<<<NB_SCAN, 512>>>();     // also re-zeros cursor
    scatter_kernel<<<NB_EDGE, 256>>>(edge_src, edge_dst, edge_w);

    // layer 0: x -> h
    gemm_kernel<128><<<NB_GEMM, 256>>>(x, W0, support, N_NODES);
    spmm_kernel<128, true><<<NB_SPMM, 256>>>(support, b0, h);
    // layer 1
    gemm_kernel<128><<<NB_GEMM, 256>>>(h, W1, support, N_NODES);
    spmm_kernel<128, true><<<NB_SPMM, 256>>>(support, b1, h);
    // layer 2
    gemm_kernel<128><<<NB_GEMM, 256>>>(h, W2, support, N_NODES);
    spmm_kernel<128, true><<<NB_SPMM, 256>>>(support, b2, h);
    // layer 3 (d=64, no relu) -> d_out
    gemm_kernel<64><<<NB_GEMM, 256>>>(h, W3, support, N_NODES);
    spmm_kernel<64, false><<<NB_SPMM, 256>>>(support, b3, out);
}

// round 7
// speedup vs baseline: 1.2757x; 1.2424x over previous
#include <cuda_runtime.h>
#include <cuda_bf16.h>

#define N_NODES 50000
#define N_EDGES 800000
#define NFEAT 128
#define NHID 128
#define NOUT 64

// ---------------- scratch (static __device__, no allocations) ----------------
__device__ __align__(16) __nv_bfloat16 g_support[N_NODES * 128];  // bf16 support
__device__ __align__(16) float g_h[N_NODES * 128];
__device__ int   g_rowptr[N_NODES + 1];
__device__ int   g_cursor[N_NODES];
__device__ int   g_blocksum[128];
__device__ int   g_csr_src[N_EDGES];
__device__ float g_csr_w[N_EDGES];

// ---------------- helpers ----------------
__device__ __forceinline__ void ffma2(unsigned long long& d,
                                      unsigned long long a,
                                      unsigned long long b) {
    asm("fma.rn.f32x2 %0, %1, %2, %0;" : "+l"(d) : "l"(a), "l"(b));
}
__device__ __forceinline__ unsigned long long dup2(float x) {
    unsigned long long r;
    asm("mov.b64 %0, {%1, %1};" : "=l"(r) : "f"(x));
    return r;
}
__device__ __forceinline__ unsigned cvt_bf2(unsigned long long pair) {
    float lo, hi; unsigned r;
    asm("mov.b64 {%0, %1}, %2;" : "=f"(lo), "=f"(hi) : "l"(pair));
    asm("cvt.rn.bf16x2.f32 %0, %1, %2;" : "=r"(r) : "f"(hi), "f"(lo));
    return r;
}
__device__ __forceinline__ float2 bf2f(unsigned bits) {
    __nv_bfloat162 h = *reinterpret_cast<const __nv_bfloat162*>(&bits);
    return __bfloat1622float2(h);
}

// ---------------- CSR build ----------------
__global__ void zero_cursor_kernel() {
    int i = blockIdx.x * blockDim.x + threadIdx.x;
    if (i < N_NODES) g_cursor[i] = 0;
}

__global__ void hist_kernel(const int* __restrict__ dst) {
    int e = blockIdx.x * blockDim.x + threadIdx.x;
    if (e < N_EDGES) atomicAdd(&g_cursor[dst[e]], 1);
}

__global__ void scan_blocks_kernel() {
    __shared__ int sdata[512];
    const int tid = threadIdx.x;
    int i = blockIdx.x * 512 + tid;
    int v = (i < N_NODES) ? g_cursor[i] : 0;
    sdata[tid] = v;
    __syncthreads();
#pragma unroll
    for (int off = 1; off < 512; off <<= 1) {
        int t = (tid >= off) ? sdata[tid - off] : 0;
        __syncthreads();
        sdata[tid] += t;
        __syncthreads();
    }
    if (i < N_NODES) g_rowptr[i] = sdata[tid] - v;
    if (tid == 511) g_blocksum[blockIdx.x] = sdata[511];
}

__global__ void scan_tops_kernel(int nblk) {
    __shared__ int sdata[128];
    const int tid = threadIdx.x;
    int v = (tid < nblk) ? g_blocksum[tid] : 0;
    sdata[tid] = v;
    __syncthreads();
#pragma unroll
    for (int off = 1; off < 128; off <<= 1) {
        int t = (tid >= off) ? sdata[tid - off] : 0;
        __syncthreads();
        sdata[tid] += t;
        __syncthreads();
    }
    if (tid < nblk) g_blocksum[tid] = sdata[tid] - v;
}

__global__ void add_offsets_kernel() {
    int i = blockIdx.x * 512 + threadIdx.x;
    if (i < N_NODES) {
        g_rowptr[i] += g_blocksum[blockIdx.x];
        g_cursor[i] = 0;
    }
    if (i == 0) g_rowptr[N_NODES] = N_EDGES;
}

__global__ void scatter_kernel(const int* __restrict__ src,
                               const int* __restrict__ dst,
                               const float* __restrict__ w) {
    int e = blockIdx.x * blockDim.x + threadIdx.x;
    if (e < N_EDGES) {
        int d = dst[e];
        int pos = g_rowptr[d] + atomicAdd(&g_cursor[d], 1);
        g_csr_src[pos] = src[e];
        g_csr_w[pos]   = w[e];
    }
}

// ---------------- dense GEMM: C[M,BN](bf16) = A[M,128](f32) @ B[128,BN](f32)
// BM=128, BK=16, double-buffered smem (48 KB), 256 threads, FFMA2 math,
// bf16x2 epilogue.
template <int BN>
__global__ void __launch_bounds__(256)
gemm_kernel(const float* __restrict__ A, const float* __restrict__ B,
            __nv_bfloat16* __restrict__ C, int M) {
    constexpr int K = 128, BM = 128, BK = 16;
    constexpr int TM = 8, TN = BN / 16, TN2 = TN / 2;
    constexpr int NSLAB = K / BK;                 // 8
    constexpr int A_IT = (BM * BK / 4) / 256;     // 2
    constexpr int B_IT = (BK * BN / 4) / 256;     // 2 (BN=128) / 1 (BN=64)

    __shared__ unsigned long long As2[2][BK][BM]; // 2 x 16 KB, {a,a} pairs
    __shared__ float Bs[2][BK][BN];               // 2 x 8/4 KB

    const int tid = threadIdx.x;
    const int m0  = blockIdx.x * BM;
    const int tx  = tid % 16;
    const int ty  = tid / 16;
    const int mm  = ty * TM;
    const int nn  = tx * TN;

    unsigned long long acc2[TM][TN2];
#pragma unroll
    for (int i = 0; i < TM; i++)
#pragma unroll
        for (int j = 0; j < TN2; j++) acc2[i][j] = 0ull;

    const float4* A4 = reinterpret_cast<const float4*>(A);
    const float4* B4 = reinterpret_cast<const float4*>(B);

    float4 areg[A_IT], breg[B_IT];

    auto load_global = [&](int s) {
#pragma unroll
        for (int it = 0; it < A_IT; it++) {
            int f  = tid + it * 256;
            int m  = f & (BM - 1);
            int kq = f >> 7;                       // 0..BK/4-1
            int gm = m0 + m;
            areg[it] = (gm < M) ? A4[gm * (K / 4) + (s * BK) / 4 + kq]
                                : make_float4(0.f, 0.f, 0.f, 0.f);
        }
#pragma unroll
        for (int it = 0; it < B_IT; it++) {
            int f = tid + it * 256;
            breg[it] = B4[(s * BK) * (BN / 4) + f];
        }
    };
    auto store_smem = [&](int buf) {
#pragma unroll
        for (int it = 0; it < A_IT; it++) {
            int f  = tid + it * 256;
            int m  = f & (BM - 1);
            int k  = (f >> 7) * 4;
            As2[buf][k + 0][m] = dup2(areg[it].x);
            As2[buf][k + 1][m] = dup2(areg[it].y);
            As2[buf][k + 2][m] = dup2(areg[it].z);
            As2[buf][k + 3][m] = dup2(areg[it].w);
        }
#pragma unroll
        for (int it = 0; it < B_IT; it++) {
            int f = tid + it * 256;
            reinterpret_cast<float4*>(&Bs[buf][0][0])[f] = breg[it];
        }
    };
    auto compute = [&](int buf) {
#pragma unroll
        for (int k = 0; k < BK; k++) {
            unsigned long long a2[TM];
#pragma unroll
            for (int i2 = 0; i2 < TM / 2; i2++) {
                ulonglong2 av = *reinterpret_cast<const ulonglong2*>(&As2[buf][k][mm + i2 * 2]);
                a2[i2 * 2 + 0] = av.x;
                a2[i2 * 2 + 1] = av.y;
            }
            unsigned long long b2[TN2];
#pragma unroll
            for (int j4 = 0; j4 < TN2 / 2; j4++) {
                ulonglong2 bv = *reinterpret_cast<const ulonglong2*>(&Bs[buf][k][nn + j4 * 4]);
                b2[j4 * 2 + 0] = bv.x;
                b2[j4 * 2 + 1] = bv.y;
            }
            if constexpr (TN2 == 2) {  // BN=64: single ulonglong2 covers TN2
            }
#pragma unroll
            for (int i = 0; i < TM; i++)
#pragma unroll
                for (int j = 0; j < TN2; j++) ffma2(acc2[i][j], a2[i], b2[j]);
        }
    };

    load_global(0);
    store_smem(0);
    __syncthreads();

    for (int s = 0; s < NSLAB; s++) {
        int cur = s & 1;
        bool has_next = (s + 1) < NSLAB;
        if (has_next) load_global(s + 1);   // LDG latency hidden by compute
        compute(cur);
        if (has_next) store_smem(cur ^ 1);
        __syncthreads();
    }

    // epilogue: pack each f32 pair -> bf16x2, vector store
#pragma unroll
    for (int i = 0; i < TM; i++) {
        int row = m0 + mm + i;
        if (row < M) {
            unsigned r32[TN2];
#pragma unroll
            for (int j = 0; j < TN2; j++) r32[j] = cvt_bf2(acc2[i][j]);
            unsigned* outp = reinterpret_cast<unsigned*>(C + row * BN + nn);
            if constexpr (TN2 == 4) {
                uint4 o = make_uint4(r32[0], r32[1], r32[2], r32[3]);
                *reinterpret_cast<uint4*>(outp) = o;
            } else {
                uint2 o = make_uint2(r32[0], r32[1]);
                *reinterpret_cast<uint2*>(outp) = o;
            }
        }
    }
}

// ---------------- SpMM (CSR-by-dst, bf16 gather) + bias (+ReLU) ----------------
// one warp per destination node; lane owns D/32 consecutive channels.
template <int D, bool RELU>
__global__ void spmm_kernel(const __nv_bfloat16* __restrict__ sup,
                            const float* __restrict__ bias,
                            float* __restrict__ out) {
    int gw = (blockIdx.x * blockDim.x + threadIdx.x) >> 5;
    if (gw >= N_NODES) return;
    int lane = threadIdx.x & 31;
    int s = g_rowptr[gw];
    int e = g_rowptr[gw + 1];

    if constexpr (D == 128) {
        const uint2* supv = reinterpret_cast<const uint2*>(sup);  // 32 uint2/row
        float4 acc = make_float4(0.f, 0.f, 0.f, 0.f);
        int i = s;
        for (; i + 3 < e; i += 4) {
            int   s0 = g_csr_src[i];     float w0 = g_csr_w[i];
            int   s1 = g_csr_src[i + 1]; float w1 = g_csr_w[i + 1];
            int   s2 = g_csr_src[i + 2]; float w2 = g_csr_w[i + 2];
            int   s3 = g_csr_src[i + 3]; float w3 = g_csr_w[i + 3];
            uint2 v0 = supv[s0 * 32 + lane];
            uint2 v1 = supv[s1 * 32 + lane];
            uint2 v2 = supv[s2 * 32 + lane];
            uint2 v3 = supv[s3 * 32 + lane];
            float2 p;
            p = bf2f(v0.x); acc.x += w0 * p.x; acc.y += w0 * p.y;
            p = bf2f(v0.y); acc.z += w0 * p.x; acc.w += w0 * p.y;
            p = bf2f(v1.x); acc.x += w1 * p.x; acc.y += w1 * p.y;
            p = bf2f(v1.y); acc.z += w1 * p.x; acc.w += w1 * p.y;
            p = bf2f(v2.x); acc.x += w2 * p.x; acc.y += w2 * p.y;
            p = bf2f(v2.y); acc.z += w2 * p.x; acc.w += w2 * p.y;
            p = bf2f(v3.x); acc.x += w3 * p.x; acc.y += w3 * p.y;
            p = bf2f(v3.y); acc.z += w3 * p.x; acc.w += w3 * p.y;
        }
        for (; i < e; i++) {
            int s0 = g_csr_src[i]; float w0 = g_csr_w[i];
            uint2 v0 = supv[s0 * 32 + lane];
            float2 p;
            p = bf2f(v0.x); acc.x += w0 * p.x; acc.y += w0 * p.y;
            p = bf2f(v0.y); acc.z += w0 * p.x; acc.w += w0 * p.y;
        }
        float4 b = reinterpret_cast<const float4*>(bias)[lane];
        acc.x += b.x; acc.y += b.y; acc.z += b.z; acc.w += b.w;
        if (RELU) {
            acc.x = fmaxf(acc.x, 0.f); acc.y = fmaxf(acc.y, 0.f);
            acc.z = fmaxf(acc.z, 0.f); acc.w = fmaxf(acc.w, 0.f);
        }
        reinterpret_cast<float4*>(out)[gw * 32 + lane] = acc;
    } else {  // D == 64
        const unsigned* supv = reinterpret_cast<const unsigned*>(sup);  // 32 u32/row
        float2 acc = make_float2(0.f, 0.f);
        int i = s;
        for (; i + 3 < e; i += 4) {
            int   s0 = g_csr_src[i];     float w0 = g_csr_w[i];
            int   s1 = g_csr_src[i + 1]; float w1 = g_csr_w[i + 1];
            int   s2 = g_csr_src[i + 2]; float w2 = g_csr_w[i + 2];
            int   s3 = g_csr_src[i + 3]; float w3 = g_csr_w[i + 3];
            unsigned v0 = supv[s0 * 32 + lane];
            unsigned v1 = supv[s1 * 32 + lane];
            unsigned v2 = supv[s2 * 32 + lane];
            unsigned v3 = supv[s3 * 32 + lane];
            float2 p;
            p = bf2f(v0); acc.x += w0 * p.x; acc.y += w0 * p.y;
            p = bf2f(v1); acc.x += w1 * p.x; acc.y += w1 * p.y;
            p = bf2f(v2); acc.x += w2 * p.x; acc.y += w2 * p.y;
            p = bf2f(v3); acc.x += w3 * p.x; acc.y += w3 * p.y;
        }
        for (; i < e; i++) {
            int s0 = g_csr_src[i]; float w0 = g_csr_w[i];
            unsigned v0 = supv[s0 * 32 + lane];
            float2 p = bf2f(v0);
            acc.x += w0 * p.x; acc.y += w0 * p.y;
        }
        float2 b = reinterpret_cast<const float2*>(bias)[lane];
        acc.x += b.x; acc.y += b.y;
        if (RELU) { acc.x = fmaxf(acc.x, 0.f); acc.y = fmaxf(acc.y, 0.f); }
        reinterpret_cast<float2*>(out)[gw * 32 + lane] = acc;
    }
}

// ---------------- launch ----------------
extern "C" void kernel_launch(void* const* d_in, const int* in_sizes, int n_in,
                              void* d_out, int out_size) {
    const float* x        = (const float*)d_in[0];
    const int*   edge_src = (const int*)  d_in[1];
    const int*   edge_dst = (const int*)  d_in[2];
    const float* edge_w   = (const float*)d_in[3];
    const float* W0 = (const float*)d_in[4];  const float* b0 = (const float*)d_in[5];
    const float* W1 = (const float*)d_in[6];  const float* b1 = (const float*)d_in[7];
    const float* W2 = (const float*)d_in[8];  const float* b2 = (const float*)d_in[9];
    const float* W3 = (const float*)d_in[10]; const float* b3 = (const float*)d_in[11];
    float* out = (float*)d_out;

    __nv_bfloat16* support; cudaGetSymbolAddress((void**)&support, g_support);
    float* h;               cudaGetSymbolAddress((void**)&h, g_h);

    const int NB_NODE = (N_NODES + 255) / 256;
    const int NB_EDGE = (N_EDGES + 255) / 256;
    const int NB_GEMM = (N_NODES + 127) / 128;
    const int NB_SPMM = (N_NODES + 7) / 8;      // 8 warps/block
    const int NB_SCAN = (N_NODES + 511) / 512;  // 98

    // CSR build (per launch; amortized over 4 layers)
    zero_cursor_kernel<<<NB_NODE, 256>>>();
    hist_kernel<<<NB_EDGE, 256>>>(edge_dst);
    scan_blocks_kernel<<<NB_SCAN, 512>>>();
    scan_tops_kernel<<<1, 128>>>(NB_SCAN);
    add_offsets_kernel<<<NB_SCAN, 512>>>();     // also re-zeros cursor
    scatter_kernel<<<NB_EDGE, 256>>>(edge_src, edge_dst, edge_w);

    // layer 0: x -> h
    gemm_kernel<128><<<NB_GEMM, 256>>>(x, W0, support, N_NODES);
    spmm_kernel<128, true><<<NB_SPMM, 256>>>(support, b0, h);
    // layer 1
    gemm_kernel<128><<<NB_GEMM, 256>>>(h, W1, support, N_NODES);
    spmm_kernel<128, true><<<NB_SPMM, 256>>>(support, b1, h);
    // layer 2
    gemm_kernel<128><<<NB_GEMM, 256>>>(h, W2, support, N_NODES);
    spmm_kernel<128, true><<<NB_SPMM, 256>>>(support, b2, h);
    // layer 3 (d=64, no relu) -> d_out
    gemm_kernel<64><<<NB_GEMM, 256>>>(h, W3, support, N_NODES);
    spmm_kernel<64, false><<<NB_SPMM, 256>>>(support, b3, out);
}